// round 2
// baseline (speedup 1.0000x reference)
#include <cuda_runtime.h>

// SSIM-with-logits fused kernel for GB300 (sm_103a).
// input:  d_in[0] = logits  (16,1,1024,1024) f32
//         d_in[1] = target  (16,1,1024,1024) f32
// output: d_out[0] = scalar mean loss (f32)

#define IMG_H 1024
#define IMG_W 1024
#define NBATCH 16
#define TW 32              // tile width  (output)
#define TH 32              // tile height (output)
#define EW 42              // extended width  (TW + 10)
#define EH 42              // extended height (TH + 10)
#define SW 43              // smem stride for s (odd -> conflict-free)
#define HW 33              // smem stride for h (odd -> conflict-free)
#define NBLK (NBATCH * (IMG_H/TH) * (IMG_W/TW))   // 16384

#define SMEM_FLOATS (5*EH*SW + 5*EH*HW)           // 9030 + 6930 = 15960
#define SMEM_BYTES  (SMEM_FLOATS * 4)             // 63840

__device__ float g_partial[NBLK];

// Normalized gaussian(sigma=1.5, ws=11) taps as literal immediates so ptxas
// emits FFMA-imm (rt_SMSP=1, 2x throughput of 3-reg FFMA).
__device__ __forceinline__ float conv11(const float* x) {
    float a =        0.00102838f * x[0];
    a = fmaf(0.00759875f, x[1],  a);
    a = fmaf(0.03600077f, x[2],  a);
    a = fmaf(0.10936084f, x[3],  a);
    a = fmaf(0.21300546f, x[4],  a);
    a = fmaf(0.26601163f, x[5],  a);
    a = fmaf(0.21300546f, x[6],  a);
    a = fmaf(0.10936084f, x[7],  a);
    a = fmaf(0.03600077f, x[8],  a);
    a = fmaf(0.00759875f, x[9],  a);
    a = fmaf(0.00102838f, x[10], a);
    return a;
}

extern __shared__ float dyn_smem[];

__global__ __launch_bounds__(256)
void ssim_tile_kernel(const float* __restrict__ logits,
                      const float* __restrict__ target) {
    float* s = dyn_smem;                 // s[5][EH][SW]  raw maps (a, b, a2, b2, ab)
    float* h = dyn_smem + 5 * EH * SW;   // h[5][EH][HW]  horizontally filtered

    const int tid   = threadIdx.x;
    const int tileC = blockIdx.x * TW;
    const int tileR = blockIdx.y * TH;
    const int b     = blockIdx.z;

    const float* inb = logits + (size_t)b * (IMG_H * IMG_W);
    const float* tgb = target + (size_t)b * (IMG_H * IMG_W);

    // ---- Phase 1: load extended tile, sigmoid, products -> smem ----------
    for (int i = tid; i < EH * EW; i += 256) {
        int er = i / EW;
        int ec = i - er * EW;
        int gr = tileR + er - 5;
        int gc = tileC + ec - 5;
        if (gr < 0) gr = -gr;
        if (gr > IMG_H - 1) gr = 2 * (IMG_H - 1) - gr;
        if (gc < 0) gc = -gc;
        if (gc > IMG_W - 1) gc = 2 * (IMG_W - 1) - gc;
        float xi = inb[gr * IMG_W + gc];
        float bt = tgb[gr * IMG_W + gc];
        float a  = __fdividef(1.0f, 1.0f + __expf(-xi));   // sigmoid
        float* sp = s + er * SW + ec;
        sp[0 * EH * SW] = a;
        sp[1 * EH * SW] = bt;
        sp[2 * EH * SW] = a * a;
        sp[3 * EH * SW] = bt * bt;
        sp[4 * EH * SW] = a * bt;
    }
    __syncthreads();

    // ---- Phase 2: horizontal pass. 1 thread per (map,row): 210 tasks ----
    if (tid < 5 * EH) {
        int m = tid / EH;
        int r = tid - m * EH;
        const float* srow = s + m * (EH * SW) + r * SW;
        float x[EW];
        #pragma unroll
        for (int i = 0; i < EW; ++i) x[i] = srow[i];
        float* hrow = h + m * (EH * HW) + r * HW;
        #pragma unroll
        for (int c = 0; c < TW; ++c)
            hrow[c] = conv11(&x[c]);
    }
    __syncthreads();

    // ---- Phase 3: vertical pass + SSIM. 1 thread per (col, 4-row strip) --
    const int c  = tid & 31;
    const int r0 = (tid >> 5) * 4;       // 8 strips * 4 rows = 32 rows

    float v[5][4];
    #pragma unroll
    for (int m = 0; m < 5; ++m) {
        const float* hcol = h + m * (EH * HW) + r0 * HW + c;
        float y[14];
        #pragma unroll
        for (int j = 0; j < 14; ++j) y[j] = hcol[j * HW];
        #pragma unroll
        for (int j = 0; j < 4; ++j) v[m][j] = conv11(&y[j]);
    }

    const float C1 = 1.0e-4f;
    const float C2 = 9.0e-4f;
    float lsum = 0.0f;
    #pragma unroll
    for (int j = 0; j < 4; ++j) {
        float mu1 = v[0][j], mu2 = v[1][j];
        float m11 = mu1 * mu1, m22 = mu2 * mu2, m12 = mu1 * mu2;
        float s11 = v[2][j] - m11;
        float s22 = v[3][j] - m22;
        float s12 = v[4][j] - m12;
        float num = (2.0f * m12 + C1) * (2.0f * s12 + C2);
        float den = (m11 + m22 + C1) * (s11 + s22 + C2);
        float l = 0.5f - 0.5f * __fdividef(num, den);
        l = fminf(fmaxf(l, 0.0f), 0.5f);
        lsum += l;
    }

    // ---- Phase 4: block reduction -> g_partial -------------------------
    #pragma unroll
    for (int o = 16; o; o >>= 1)
        lsum += __shfl_xor_sync(0xffffffffu, lsum, o);
    __shared__ float wsum[8];
    if ((tid & 31) == 0) wsum[tid >> 5] = lsum;
    __syncthreads();
    if (tid == 0) {
        float t = 0.0f;
        #pragma unroll
        for (int i = 0; i < 8; ++i) t += wsum[i];
        int bid = (blockIdx.z * gridDim.y + blockIdx.y) * gridDim.x + blockIdx.x;
        g_partial[bid] = t;
    }
}

__global__ __launch_bounds__(256)
void ssim_reduce_kernel(float* __restrict__ out) {
    double acc = 0.0;
    for (int i = threadIdx.x; i < NBLK; i += 256)
        acc += (double)g_partial[i];
    #pragma unroll
    for (int o = 16; o; o >>= 1)
        acc += __shfl_xor_sync(0xffffffffu, acc, o);
    __shared__ double wsum[8];
    if ((threadIdx.x & 31) == 0) wsum[threadIdx.x >> 5] = acc;
    __syncthreads();
    if (threadIdx.x == 0) {
        double t = 0.0;
        #pragma unroll
        for (int i = 0; i < 8; ++i) t += wsum[i];
        out[0] = (float)(t * (1.0 / ((double)NBATCH * IMG_H * IMG_W)));
    }
}

extern "C" void kernel_launch(void* const* d_in, const int* in_sizes, int n_in,
                              void* d_out, int out_size) {
    const float* logits = (const float*)d_in[0];
    const float* target = (const float*)d_in[1];
    float* out = (float*)d_out;

    cudaFuncSetAttribute(ssim_tile_kernel,
                         cudaFuncAttributeMaxDynamicSharedMemorySize, SMEM_BYTES);

    dim3 grid(IMG_W / TW, IMG_H / TH, NBATCH);   // 32 x 32 x 16
    ssim_tile_kernel<<<grid, 256, SMEM_BYTES>>>(logits, target);
    ssim_reduce_kernel<<<1, 256>>>(out);
}

// round 4
// speedup vs baseline: 1.1885x; 1.1885x over previous
#include <cuda_runtime.h>

// SSIM-with-logits fused kernel for GB300 (sm_103a).
// input:  d_in[0] = logits  (16,1,1024,1024) f32
//         d_in[1] = target  (16,1,1024,1024) f32
// output: d_out[0] = scalar mean loss (f32)

#define IMG_H 1024
#define IMG_W 1024
#define NBATCH 16
#define TW 32              // tile width  (output)
#define TH 32              // tile height (output)
#define EW 42              // extended width  (TW + 10)
#define EH 42              // extended height (TH + 10)
#define SW 43              // smem stride for s (odd -> conflict-free)
#define HW 33              // smem stride for h (odd -> conflict-free)
#define NBLK (NBATCH * (IMG_H/TH) * (IMG_W/TW))   // 16384

// s: 2 raw maps (a=sigmoid(logits), b=target); products computed in phase 2.
// h: 5 horizontally filtered maps.
#define S_FLOATS (2*EH*SW)                 // 3612
#define H_FLOATS (5*EH*HW)                 // 6930
#define SMEM_FLOATS (S_FLOATS + H_FLOATS)  // 10542
#define SMEM_BYTES  (SMEM_FLOATS * 4)      // 42168

__device__ float g_partial[NBLK];

// Normalized gaussian(sigma=1.5, ws=11) taps as literal immediates so ptxas
// emits FFMA-imm (rt_SMSP=1, 2x throughput of 3-reg FFMA).
__device__ __forceinline__ float conv11(const float* x) {
    float a =        0.00102838f * x[0];
    a = fmaf(0.00759875f, x[1],  a);
    a = fmaf(0.03600077f, x[2],  a);
    a = fmaf(0.10936084f, x[3],  a);
    a = fmaf(0.21300546f, x[4],  a);
    a = fmaf(0.26601163f, x[5],  a);
    a = fmaf(0.21300546f, x[6],  a);
    a = fmaf(0.10936084f, x[7],  a);
    a = fmaf(0.03600077f, x[8],  a);
    a = fmaf(0.00759875f, x[9],  a);
    a = fmaf(0.00102838f, x[10], a);
    return a;
}

extern __shared__ float dyn_smem[];

__global__ __launch_bounds__(256, 5)
void ssim_tile_kernel(const float* __restrict__ logits,
                      const float* __restrict__ target) {
    float* sa = dyn_smem;                // sa[EH][SW]   sigmoid(logits)
    float* sb = dyn_smem + EH * SW;      // sb[EH][SW]   target
    float* h  = dyn_smem + S_FLOATS;     // h[5][EH][HW] horizontally filtered

    const int tid   = threadIdx.x;
    const int tileC = blockIdx.x * TW;
    const int tileR = blockIdx.y * TH;
    const int bz    = blockIdx.z;

    const float* inb = logits + (size_t)bz * (IMG_H * IMG_W);
    const float* tgb = target + (size_t)bz * (IMG_H * IMG_W);

    // ---- Phase 1: load extended tile, sigmoid -> smem (a, b only) --------
    for (int i = tid; i < EH * EW; i += 256) {
        int er = i / EW;
        int ec = i - er * EW;
        int gr = tileR + er - 5;
        int gc = tileC + ec - 5;
        if (gr < 0) gr = -gr;
        if (gr > IMG_H - 1) gr = 2 * (IMG_H - 1) - gr;
        if (gc < 0) gc = -gc;
        if (gc > IMG_W - 1) gc = 2 * (IMG_W - 1) - gc;
        float xi = inb[gr * IMG_W + gc];
        float bt = tgb[gr * IMG_W + gc];
        float a  = __fdividef(1.0f, 1.0f + __expf(-xi));   // sigmoid
        sa[er * SW + ec] = a;
        sb[er * SW + ec] = bt;
    }
    __syncthreads();

    // ---- Phase 2: horizontal pass; products computed on the fly ----------
    // Task = (map m, row r); 210 tasks. Two 16-output chunks keep regs low.
    if (tid < 5 * EH) {
        int m = tid / EH;
        int r = tid - m * EH;
        const float* arow = sa + r * SW;
        const float* brow = sb + r * SW;
        float* hrow = h + m * (EH * HW) + r * HW;
        #pragma unroll
        for (int chunk = 0; chunk < 2; ++chunk) {
            const int base = chunk * 16;
            float w[26];
            if (m == 0) {
                #pragma unroll
                for (int i = 0; i < 26; ++i) w[i] = arow[base + i];
            } else if (m == 1) {
                #pragma unroll
                for (int i = 0; i < 26; ++i) w[i] = brow[base + i];
            } else if (m == 2) {
                #pragma unroll
                for (int i = 0; i < 26; ++i) { float v = arow[base + i]; w[i] = v * v; }
            } else if (m == 3) {
                #pragma unroll
                for (int i = 0; i < 26; ++i) { float v = brow[base + i]; w[i] = v * v; }
            } else {
                #pragma unroll
                for (int i = 0; i < 26; ++i) w[i] = arow[base + i] * brow[base + i];
            }
            #pragma unroll
            for (int c = 0; c < 16; ++c)
                hrow[base + c] = conv11(&w[c]);
        }
    }
    __syncthreads();

    // ---- Phase 3: vertical pass + SSIM. 1 thread per (col, 4-row strip) --
    const int c  = tid & 31;
    const int r0 = (tid >> 5) * 4;       // 8 strips * 4 rows = 32 rows

    float v[5][4];
    #pragma unroll
    for (int m = 0; m < 5; ++m) {
        const float* hcol = h + m * (EH * HW) + r0 * HW + c;
        float y[14];
        #pragma unroll
        for (int j = 0; j < 14; ++j) y[j] = hcol[j * HW];
        #pragma unroll
        for (int j = 0; j < 4; ++j) v[m][j] = conv11(&y[j]);
    }

    const float C1 = 1.0e-4f;
    const float C2 = 9.0e-4f;
    float lsum = 0.0f;
    #pragma unroll
    for (int j = 0; j < 4; ++j) {
        float mu1 = v[0][j], mu2 = v[1][j];
        float m11 = mu1 * mu1, m22 = mu2 * mu2, m12 = mu1 * mu2;
        float s11 = v[2][j] - m11;
        float s22 = v[3][j] - m22;
        float s12 = v[4][j] - m12;
        float num = (2.0f * m12 + C1) * (2.0f * s12 + C2);
        float den = (m11 + m22 + C1) * (s11 + s22 + C2);
        float l = 0.5f - 0.5f * __fdividef(num, den);
        l = fminf(fmaxf(l, 0.0f), 0.5f);
        lsum += l;
    }

    // ---- Phase 4: block reduction -> g_partial -------------------------
    #pragma unroll
    for (int o = 16; o; o >>= 1)
        lsum += __shfl_xor_sync(0xffffffffu, lsum, o);
    __shared__ float wsum[8];
    if ((tid & 31) == 0) wsum[tid >> 5] = lsum;
    __syncthreads();
    if (tid == 0) {
        float t = 0.0f;
        #pragma unroll
        for (int i = 0; i < 8; ++i) t += wsum[i];
        int bid = (blockIdx.z * gridDim.y + blockIdx.y) * gridDim.x + blockIdx.x;
        g_partial[bid] = t;
    }
}

__global__ __launch_bounds__(1024)
void ssim_reduce_kernel(float* __restrict__ out) {
    const int tid = threadIdx.x;
    const float4* p = (const float4*)g_partial;
    double acc = 0.0;
    #pragma unroll
    for (int i = 0; i < NBLK / 4 / 1024; ++i) {
        float4 q = p[tid + i * 1024];
        acc += (double)q.x + (double)q.y + (double)q.z + (double)q.w;
    }
    #pragma unroll
    for (int o = 16; o; o >>= 1)
        acc += __shfl_xor_sync(0xffffffffu, acc, o);
    __shared__ double wsum[32];
    if ((tid & 31) == 0) wsum[tid >> 5] = acc;
    __syncthreads();
    if (tid == 0) {
        double t = 0.0;
        #pragma unroll
        for (int i = 0; i < 32; ++i) t += wsum[i];
        out[0] = (float)(t * (1.0 / ((double)NBATCH * IMG_H * IMG_W)));
    }
}

extern "C" void kernel_launch(void* const* d_in, const int* in_sizes, int n_in,
                              void* d_out, int out_size) {
    const float* logits = (const float*)d_in[0];
    const float* target = (const float*)d_in[1];
    float* out = (float*)d_out;

    cudaFuncSetAttribute(ssim_tile_kernel,
                         cudaFuncAttributeMaxDynamicSharedMemorySize, SMEM_BYTES);

    dim3 grid(IMG_W / TW, IMG_H / TH, NBATCH);   // 32 x 32 x 16
    ssim_tile_kernel<<<grid, 256, SMEM_BYTES>>>(logits, target);
    ssim_reduce_kernel<<<1, 1024>>>(out);
}

// round 5
// speedup vs baseline: 1.3908x; 1.1702x over previous
#include <cuda_runtime.h>

// SSIM-with-logits fused kernel for GB300 (sm_103a), single-kernel version.
// input:  d_in[0] = logits  (16,1,1024,1024) f32
//         d_in[1] = target  (16,1,1024,1024) f32
// output: d_out[0] = scalar mean loss (f32)

#define IMG_H 1024
#define IMG_W 1024
#define NBATCH 16
#define TW 32              // tile width  (output)
#define TH 32              // tile height (output)
#define EW 42              // extended width  (TW + 10)
#define EH 42              // extended height (TH + 10)
#define SW 49              // smem stride for s rows (48 cols used; odd -> conflict-free)
#define HW 33              // smem stride for h (odd -> conflict-free)
#define NBLK (NBATCH * (IMG_H/TH) * (IMG_W/TW))   // 16384

// s: 2 raw maps (a=sigmoid(logits), b=target) over 48-wide aligned window.
// h: 5 horizontally filtered maps.
#define S_FLOATS (2*EH*SW)                 // 4116
#define H_FLOATS (5*EH*HW)                 // 6930
#define SMEM_FLOATS (S_FLOATS + H_FLOATS)  // 11046
#define SMEM_BYTES  (SMEM_FLOATS * 4)      // 44184

__device__ float    g_partial[NBLK];
__device__ unsigned g_count = 0;

// Normalized gaussian(sigma=1.5, ws=11) taps as literal immediates so ptxas
// emits FFMA-imm (rt_SMSP=1, 2x throughput of 3-reg FFMA).
__device__ __forceinline__ float conv11(const float* x) {
    float a =        0.00102838f * x[0];
    a = fmaf(0.00759875f, x[1],  a);
    a = fmaf(0.03600077f, x[2],  a);
    a = fmaf(0.10936084f, x[3],  a);
    a = fmaf(0.21300546f, x[4],  a);
    a = fmaf(0.26601163f, x[5],  a);
    a = fmaf(0.21300546f, x[6],  a);
    a = fmaf(0.10936084f, x[7],  a);
    a = fmaf(0.03600077f, x[8],  a);
    a = fmaf(0.00759875f, x[9],  a);
    a = fmaf(0.00102838f, x[10], a);
    return a;
}

__device__ __forceinline__ float fast_sigmoid(float x) {
    return __fdividef(1.0f, 1.0f + __expf(-x));
}

extern __shared__ float dyn_smem[];

__global__ __launch_bounds__(256, 5)
void ssim_tile_kernel(const float* __restrict__ logits,
                      const float* __restrict__ target,
                      float* __restrict__ out) {
    float* sa = dyn_smem;                // sa[EH][SW]   sigmoid(logits)
    float* sb = dyn_smem + EH * SW;      // sb[EH][SW]   target
    float* h  = dyn_smem + S_FLOATS;     // h[5][EH][HW] horizontally filtered

    const int tid   = threadIdx.x;
    const int tileC = blockIdx.x * TW;
    const int tileR = blockIdx.y * TH;
    const int bz    = blockIdx.z;

    const float* inb = logits + (size_t)bz * (IMG_H * IMG_W);
    const float* tgb = target + (size_t)bz * (IMG_H * IMG_W);

    // Smem column ec2 corresponds to global column gc = tileC - 8 + ec2.
    // Phase 2 reads ec2 in [3, 45); interior fast path fills [0, 48).
    const bool interior = (blockIdx.x > 0) & (blockIdx.x < (IMG_W/TW - 1)) &
                          (blockIdx.y > 0) & (blockIdx.y < (IMG_H/TH - 1));

    if (interior) {
        // ---- Phase 1 (fast): aligned float4 loads, no reflection --------
        // 42 rows x 12 float4 covering cols [tileC-8, tileC+40).
        #pragma unroll
        for (int it = 0; it < 2; ++it) {
            int i = tid + it * 256;
            if (i < EH * 12) {
                int er = i / 12;
                int q  = i - er * 12;
                const float4* pr = (const float4*)(inb + (tileR + er - 5) * IMG_W + (tileC - 8));
                const float4* pt = (const float4*)(tgb + (tileR + er - 5) * IMG_W + (tileC - 8));
                float4 xv = pr[q];
                float4 tv = pt[q];
                float* par = sa + er * SW + 4 * q;
                float* pbr = sb + er * SW + 4 * q;
                par[0] = fast_sigmoid(xv.x);
                par[1] = fast_sigmoid(xv.y);
                par[2] = fast_sigmoid(xv.z);
                par[3] = fast_sigmoid(xv.w);
                pbr[0] = tv.x; pbr[1] = tv.y; pbr[2] = tv.z; pbr[3] = tv.w;
            }
        }
    } else {
        // ---- Phase 1 (generic): per-element reflect padding -------------
        for (int i = tid; i < EH * EW; i += 256) {
            int er = i / EW;
            int ec = i - er * EW;
            int gr = tileR + er - 5;
            int gc = tileC + ec - 5;
            if (gr < 0) gr = -gr;
            if (gr > IMG_H - 1) gr = 2 * (IMG_H - 1) - gr;
            if (gc < 0) gc = -gc;
            if (gc > IMG_W - 1) gc = 2 * (IMG_W - 1) - gc;
            float xi = inb[gr * IMG_W + gc];
            float bt = tgb[gr * IMG_W + gc];
            sa[er * SW + ec + 3] = fast_sigmoid(xi);
            sb[er * SW + ec + 3] = bt;
        }
    }
    __syncthreads();

    // ---- Phase 2: horizontal pass; products computed on the fly ----------
    // Task = (map m, row r); 210 tasks. Two 16-output chunks keep regs low.
    if (tid < 5 * EH) {
        int m = tid / EH;
        int r = tid - m * EH;
        const float* arow = sa + r * SW;
        const float* brow = sb + r * SW;
        float* hrow = h + m * (EH * HW) + r * HW;
        #pragma unroll
        for (int chunk = 0; chunk < 2; ++chunk) {
            const int base = chunk * 16;
            float w[26];
            if (m == 0) {
                #pragma unroll
                for (int i = 0; i < 26; ++i) w[i] = arow[base + 3 + i];
            } else if (m == 1) {
                #pragma unroll
                for (int i = 0; i < 26; ++i) w[i] = brow[base + 3 + i];
            } else if (m == 2) {
                #pragma unroll
                for (int i = 0; i < 26; ++i) { float v = arow[base + 3 + i]; w[i] = v * v; }
            } else if (m == 3) {
                #pragma unroll
                for (int i = 0; i < 26; ++i) { float v = brow[base + 3 + i]; w[i] = v * v; }
            } else {
                #pragma unroll
                for (int i = 0; i < 26; ++i) w[i] = arow[base + 3 + i] * brow[base + 3 + i];
            }
            #pragma unroll
            for (int c = 0; c < 16; ++c)
                hrow[base + c] = conv11(&w[c]);
        }
    }
    __syncthreads();

    // ---- Phase 3: vertical pass + SSIM. 1 thread per (col, 4-row strip) --
    const int c  = tid & 31;
    const int r0 = (tid >> 5) * 4;       // 8 strips * 4 rows = 32 rows

    float v[5][4];
    #pragma unroll
    for (int m = 0; m < 5; ++m) {
        const float* hcol = h + m * (EH * HW) + r0 * HW + c;
        float y[14];
        #pragma unroll
        for (int j = 0; j < 14; ++j) y[j] = hcol[j * HW];
        #pragma unroll
        for (int j = 0; j < 4; ++j) v[m][j] = conv11(&y[j]);
    }

    const float C1 = 1.0e-4f;
    const float C2 = 9.0e-4f;
    float lsum = 0.0f;
    #pragma unroll
    for (int j = 0; j < 4; ++j) {
        float mu1 = v[0][j], mu2 = v[1][j];
        float m11 = mu1 * mu1, m22 = mu2 * mu2, m12 = mu1 * mu2;
        float s11 = v[2][j] - m11;
        float s22 = v[3][j] - m22;
        float s12 = v[4][j] - m12;
        float num = (2.0f * m12 + C1) * (2.0f * s12 + C2);
        float den = (m11 + m22 + C1) * (s11 + s22 + C2);
        float l = 0.5f - 0.5f * __fdividef(num, den);
        l = fminf(fmaxf(l, 0.0f), 0.5f);
        lsum += l;
    }

    // ---- Phase 4: block reduction -> g_partial -------------------------
    #pragma unroll
    for (int o = 16; o; o >>= 1)
        lsum += __shfl_xor_sync(0xffffffffu, lsum, o);
    __shared__ float wsum[8];
    __shared__ bool  is_last;
    if ((tid & 31) == 0) wsum[tid >> 5] = lsum;
    __syncthreads();
    if (tid == 0) {
        float t = 0.0f;
        #pragma unroll
        for (int i = 0; i < 8; ++i) t += wsum[i];
        int bid = (blockIdx.z * gridDim.y + blockIdx.y) * gridDim.x + blockIdx.x;
        g_partial[bid] = t;
        __threadfence();
        // Wrapping atomic: returns to 0 after NBLK increments -> graph-replay safe.
        unsigned old = atomicInc(&g_count, NBLK - 1);
        is_last = (old == NBLK - 1);
    }
    __syncthreads();

    // ---- Phase 5: last block performs the deterministic final sum -------
    if (is_last) {
        __threadfence();
        const float4* p = (const float4*)g_partial;
        double acc = 0.0;
        #pragma unroll
        for (int i = 0; i < NBLK / 4 / 256; ++i) {     // 16 iterations
            float4 q = __ldcg(&p[tid + i * 256]);
            acc += (double)q.x + (double)q.y + (double)q.z + (double)q.w;
        }
        #pragma unroll
        for (int o = 16; o; o >>= 1)
            acc += __shfl_xor_sync(0xffffffffu, acc, o);
        __shared__ double dsum[8];
        if ((tid & 31) == 0) dsum[tid >> 5] = acc;
        __syncthreads();
        if (tid == 0) {
            double t = 0.0;
            #pragma unroll
            for (int i = 0; i < 8; ++i) t += dsum[i];
            out[0] = (float)(t * (1.0 / ((double)NBATCH * IMG_H * IMG_W)));
        }
    }
}

extern "C" void kernel_launch(void* const* d_in, const int* in_sizes, int n_in,
                              void* d_out, int out_size) {
    const float* logits = (const float*)d_in[0];
    const float* target = (const float*)d_in[1];
    float* out = (float*)d_out;

    cudaFuncSetAttribute(ssim_tile_kernel,
                         cudaFuncAttributeMaxDynamicSharedMemorySize, SMEM_BYTES);

    dim3 grid(IMG_W / TW, IMG_H / TH, NBATCH);   // 32 x 32 x 16
    ssim_tile_kernel<<<grid, 256, SMEM_BYTES>>>(logits, target, out);
}

// round 8
// speedup vs baseline: 1.4055x; 1.0106x over previous
#include <cuda_runtime.h>

// SSIM-with-logits fused kernel for GB300 (sm_103a), single-kernel version.
// input:  d_in[0] = logits  (16,1,1024,1024) f32
//         d_in[1] = target  (16,1,1024,1024) f32
// output: d_out[0] = scalar mean loss (f32)

#define IMG_H 1024
#define IMG_W 1024
#define NBATCH 16
#define TW 32              // tile width  (output)
#define TH 32              // tile height (output)
#define EW 42              // extended width  (TW + 10)
#define EH 42              // extended height (TH + 10)
#define SW 49              // smem stride for s rows (48 cols used; odd -> conflict-free)
#define HT 42              // h transposed: stride per column (42%32=10 -> conflict-free pairs)
#define MS (TW * HT)       // per-map size of transposed h (1344 floats)
#define NBLK (NBATCH * (IMG_H/TH) * (IMG_W/TW))   // 16384

#define S_FLOATS (2*EH*SW)                 // 4116
#define H_FLOATS (5*MS)                    // 6720
#define SMEM_FLOATS (S_FLOATS + H_FLOATS)  // 10836
#define SMEM_BYTES  (SMEM_FLOATS * 4)      // 43344

__device__ float    g_partial[NBLK];
__device__ unsigned g_count = 0;

typedef unsigned long long u64;

// ---- f32x2 packed helpers (sm_103a) ---------------------------------------
__device__ __forceinline__ u64 pack2(float lo, float hi) {
    u64 r;
    asm("mov.b64 %0, {%1, %2};" : "=l"(r) : "r"(__float_as_uint(lo)), "r"(__float_as_uint(hi)));
    return r;
}
__device__ __forceinline__ void unpack2(u64 v, float& lo, float& hi) {
    unsigned a, b;
    asm("mov.b64 {%0, %1}, %2;" : "=r"(a), "=r"(b) : "l"(v));
    lo = __uint_as_float(a); hi = __uint_as_float(b);
}
__device__ __forceinline__ u64 fma2(u64 a, u64 b, u64 c) {
    u64 d; asm("fma.rn.f32x2 %0, %1, %2, %3;" : "=l"(d) : "l"(a), "l"(b), "l"(c)); return d;
}
__device__ __forceinline__ u64 mul2(u64 a, u64 b) {
    u64 d; asm("mul.rn.f32x2 %0, %1, %2;" : "=l"(d) : "l"(a), "l"(b)); return d;
}
__device__ __forceinline__ u64 add2(u64 a, u64 b) {
    u64 d; asm("add.rn.f32x2 %0, %1, %2;" : "=l"(d) : "l"(a), "l"(b)); return d;
}
// broadcast a compile-time float into both lanes (folds to a 64-bit immediate)
__device__ __forceinline__ u64 wpair(float w) {
    unsigned u = __float_as_uint(w);
    return (((u64)u) << 32) | (u64)u;
}

// Gaussian(sigma=1.5, ws=11) taps
#define G0 0.00102838f
#define G1 0.00759875f
#define G2 0.03600077f
#define G3 0.10936084f
#define G4 0.21300546f
#define G5 0.26601163f

// Scalar horizontal conv (FFMA-imm, rt_SMSP=1)
__device__ __forceinline__ float conv11(const float* x) {
    float a =  G0 * x[0];
    a = fmaf(G1, x[1],  a);
    a = fmaf(G2, x[2],  a);
    a = fmaf(G3, x[3],  a);
    a = fmaf(G4, x[4],  a);
    a = fmaf(G5, x[5],  a);
    a = fmaf(G4, x[6],  a);
    a = fmaf(G3, x[7],  a);
    a = fmaf(G2, x[8],  a);
    a = fmaf(G1, x[9],  a);
    a = fmaf(G0, x[10], a);
    return a;
}

// Packed vertical conv for one map: produces out-row pairs (r0,r0+1) and (r0+2,r0+3).
// hc points at h[m][c][r0] (8B aligned). Loads 14 floats as 7 LDS.64.
__device__ __forceinline__ void vconv(const float* hc, u64& vA, u64& vB) {
    const u64* hp = (const u64*)hc;
    u64 A0 = hp[0], A1 = hp[1], A2 = hp[2], A3 = hp[3], A4 = hp[4], A5 = hp[5], A6 = hp[6];
    float l0,h0,l1,h1,l2,h2,l3,h3,l4,h4,l5,h5,l6,h6;
    unpack2(A0,l0,h0); unpack2(A1,l1,h1); unpack2(A2,l2,h2); unpack2(A3,l3,h3);
    unpack2(A4,l4,h4); unpack2(A5,l5,h5); unpack2(A6,l6,h6);
    u64 p1  = pack2(h0, l1);
    u64 p3  = pack2(h1, l2);
    u64 p5  = pack2(h2, l3);
    u64 p7  = pack2(h3, l4);
    u64 p9  = pack2(h4, l5);
    u64 p11 = pack2(h5, l6);
    u64 a;
    a = mul2(A0, wpair(G0));
    a = fma2(p1, wpair(G1), a);  a = fma2(A1, wpair(G2), a);
    a = fma2(p3, wpair(G3), a);  a = fma2(A2, wpair(G4), a);
    a = fma2(p5, wpair(G5), a);  a = fma2(A3, wpair(G4), a);
    a = fma2(p7, wpair(G3), a);  a = fma2(A4, wpair(G2), a);
    a = fma2(p9, wpair(G1), a);  a = fma2(A5, wpair(G0), a);
    vA = a;
    u64 b;
    b = mul2(A1, wpair(G0));
    b = fma2(p3, wpair(G1), b);  b = fma2(A2, wpair(G2), b);
    b = fma2(p5, wpair(G3), b);  b = fma2(A3, wpair(G4), b);
    b = fma2(p7, wpair(G5), b);  b = fma2(A4, wpair(G4), b);
    b = fma2(p9, wpair(G3), b);  b = fma2(A5, wpair(G2), b);
    b = fma2(p11, wpair(G1), b); b = fma2(A6, wpair(G0), b);
    vB = b;
}

__device__ __forceinline__ float fast_sigmoid(float x) {
    return __fdividef(1.0f, 1.0f + __expf(-x));
}

extern __shared__ float dyn_smem[];

__global__ __launch_bounds__(256, 5)
void ssim_tile_kernel(const float* __restrict__ logits,
                      const float* __restrict__ target,
                      float* __restrict__ out) {
    float* sa = dyn_smem;                // sa[EH][SW]   sigmoid(logits)
    float* sb = dyn_smem + EH * SW;      // sb[EH][SW]   target
    float* h  = dyn_smem + S_FLOATS;     // h[5][TW cols][HT rows]  (transposed!)

    const int tid   = threadIdx.x;
    const int tileC = blockIdx.x * TW;
    const int tileR = blockIdx.y * TH;
    const int bz    = blockIdx.z;

    const float* inb = logits + (size_t)bz * (IMG_H * IMG_W);
    const float* tgb = target + (size_t)bz * (IMG_H * IMG_W);

    const bool interior = (blockIdx.x > 0) & (blockIdx.x < (IMG_W/TW - 1)) &
                          (blockIdx.y > 0) & (blockIdx.y < (IMG_H/TH - 1));

    if (interior) {
        // ---- Phase 1 (fast): aligned float4 loads, no reflection --------
        #pragma unroll
        for (int it = 0; it < 2; ++it) {
            int i = tid + it * 256;
            if (i < EH * 12) {
                int er = i / 12;
                int q  = i - er * 12;
                const float4* pr = (const float4*)(inb + (tileR + er - 5) * IMG_W + (tileC - 8));
                const float4* pt = (const float4*)(tgb + (tileR + er - 5) * IMG_W + (tileC - 8));
                float4 xv = pr[q];
                float4 tv = pt[q];
                float* par = sa + er * SW + 4 * q;
                float* pbr = sb + er * SW + 4 * q;
                par[0] = fast_sigmoid(xv.x);
                par[1] = fast_sigmoid(xv.y);
                par[2] = fast_sigmoid(xv.z);
                par[3] = fast_sigmoid(xv.w);
                pbr[0] = tv.x; pbr[1] = tv.y; pbr[2] = tv.z; pbr[3] = tv.w;
            }
        }
    } else {
        // ---- Phase 1 (generic): per-element reflect padding -------------
        for (int i = tid; i < EH * EW; i += 256) {
            int er = i / EW;
            int ec = i - er * EW;
            int gr = tileR + er - 5;
            int gc = tileC + ec - 5;
            if (gr < 0) gr = -gr;
            if (gr > IMG_H - 1) gr = 2 * (IMG_H - 1) - gr;
            if (gc < 0) gc = -gc;
            if (gc > IMG_W - 1) gc = 2 * (IMG_W - 1) - gc;
            float xi = inb[gr * IMG_W + gc];
            float bt = tgb[gr * IMG_W + gc];
            sa[er * SW + ec + 3] = fast_sigmoid(xi);
            sb[er * SW + ec + 3] = bt;
        }
    }
    __syncthreads();

    // ---- Phase 2: horizontal pass -> transposed h ------------------------
    if (tid < 5 * EH) {
        int m = tid / EH;
        int r = tid - m * EH;
        const float* arow = sa + r * SW;
        const float* brow = sb + r * SW;
        float* hdst = h + m * MS + r;         // + col*HT per output
        #pragma unroll
        for (int chunk = 0; chunk < 2; ++chunk) {
            const int base = chunk * 16;
            float w[26];
            if (m == 0) {
                #pragma unroll
                for (int i = 0; i < 26; ++i) w[i] = arow[base + 3 + i];
            } else if (m == 1) {
                #pragma unroll
                for (int i = 0; i < 26; ++i) w[i] = brow[base + 3 + i];
            } else if (m == 2) {
                #pragma unroll
                for (int i = 0; i < 26; ++i) { float v = arow[base + 3 + i]; w[i] = v * v; }
            } else if (m == 3) {
                #pragma unroll
                for (int i = 0; i < 26; ++i) { float v = brow[base + 3 + i]; w[i] = v * v; }
            } else {
                #pragma unroll
                for (int i = 0; i < 26; ++i) w[i] = arow[base + 3 + i] * brow[base + 3 + i];
            }
            #pragma unroll
            for (int c = 0; c < 16; ++c)
                hdst[(base + c) * HT] = conv11(&w[c]);
        }
    }
    __syncthreads();

    // ---- Phase 3: packed vertical pass + SSIM ----------------------------
    // Thread (c, strip): out rows (r0..r0+3) as two f32x2 pairs A=(r0,r0+1), B=(r0+2,r0+3).
    const int c  = tid & 31;
    const int r0 = (tid >> 5) * 4;
    const float* hb = h + c * HT + r0;

    const u64 C1p = wpair(1.0e-4f);
    const u64 C2p = wpair(9.0e-4f);
    const u64 TWOp = wpair(2.0f);
    const u64 N1p = wpair(-1.0f);

    u64 muA1, muB1, muA2, muB2;
    vconv(hb + 0 * MS, muA1, muB1);
    vconv(hb + 1 * MS, muA2, muB2);

    u64 m12A  = mul2(muA1, muA2);
    u64 m12B  = mul2(muB1, muB2);
    u64 den1A = fma2(muA2, muA2, fma2(muA1, muA1, C1p));   // m11+m22+C1
    u64 den1B = fma2(muB2, muB2, fma2(muB1, muB1, C1p));
    u64 msumA = fma2(C1p, N1p, den1A);                      // m11+m22
    u64 msumB = fma2(C1p, N1p, den1B);
    // mu registers die here

    u64 eA2, eB2, tA, tB;
    vconv(hb + 2 * MS, eA2, eB2);   // E[a^2]
    vconv(hb + 3 * MS, tA, tB);     // E[b^2]
    u64 sEA = add2(eA2, tA);
    u64 sEB = add2(eB2, tB);

    u64 eabA, eabB;
    vconv(hb + 4 * MS, eabA, eabB); // E[ab]

    u64 den2A = add2(fma2(msumA, N1p, sEA), C2p);  // s11+s22+C2
    u64 den2B = add2(fma2(msumB, N1p, sEB), C2p);
    u64 s12A  = fma2(m12A, N1p, eabA);             // sigma12
    u64 s12B  = fma2(m12B, N1p, eabB);
    u64 numA  = mul2(fma2(TWOp, m12A, C1p), fma2(TWOp, s12A, C2p));
    u64 numB  = mul2(fma2(TWOp, m12B, C1p), fma2(TWOp, s12B, C2p));
    u64 denA  = mul2(den1A, den2A);
    u64 denB  = mul2(den1B, den2B);

    float n0, n1, n2, n3, d0, d1, d2, d3;
    unpack2(numA, n0, n1); unpack2(numB, n2, n3);
    unpack2(denA, d0, d1); unpack2(denB, d2, d3);

    float lsum = 0.0f;
    {
        float l;
        l = 0.5f - 0.5f * __fdividef(n0, d0); lsum += fminf(fmaxf(l, 0.0f), 0.5f);
        l = 0.5f - 0.5f * __fdividef(n1, d1); lsum += fminf(fmaxf(l, 0.0f), 0.5f);
        l = 0.5f - 0.5f * __fdividef(n2, d2); lsum += fminf(fmaxf(l, 0.0f), 0.5f);
        l = 0.5f - 0.5f * __fdividef(n3, d3); lsum += fminf(fmaxf(l, 0.0f), 0.5f);
    }

    // ---- Phase 4: block reduction -> g_partial -------------------------
    #pragma unroll
    for (int o = 16; o; o >>= 1)
        lsum += __shfl_xor_sync(0xffffffffu, lsum, o);
    __shared__ float wsum[8];
    __shared__ bool  is_last;
    if ((tid & 31) == 0) wsum[tid >> 5] = lsum;
    __syncthreads();
    if (tid == 0) {
        float t = 0.0f;
        #pragma unroll
        for (int i = 0; i < 8; ++i) t += wsum[i];
        int bid = (blockIdx.z * gridDim.y + blockIdx.y) * gridDim.x + blockIdx.x;
        g_partial[bid] = t;
        __threadfence();
        unsigned old = atomicInc(&g_count, NBLK - 1);
        is_last = (old == NBLK - 1);
    }
    __syncthreads();

    // ---- Phase 5: last block performs the deterministic final sum -------
    if (is_last) {
        __threadfence();
        const float4* p = (const float4*)g_partial;
        double acc = 0.0;
        #pragma unroll
        for (int i = 0; i < NBLK / 4 / 256; ++i) {     // 16 iterations
            float4 q = __ldcg(&p[tid + i * 256]);
            acc += (double)q.x + (double)q.y + (double)q.z + (double)q.w;
        }
        #pragma unroll
        for (int o = 16; o; o >>= 1)
            acc += __shfl_xor_sync(0xffffffffu, acc, o);
        __shared__ double dsum[8];
        if ((tid & 31) == 0) dsum[tid >> 5] = acc;
        __syncthreads();
        if (tid == 0) {
            double t = 0.0;
            #pragma unroll
            for (int i = 0; i < 8; ++i) t += dsum[i];
            out[0] = (float)(t * (1.0 / ((double)NBATCH * IMG_H * IMG_W)));
        }
    }
}

extern "C" void kernel_launch(void* const* d_in, const int* in_sizes, int n_in,
                              void* d_out, int out_size) {
    const float* logits = (const float*)d_in[0];
    const float* target = (const float*)d_in[1];
    float* out = (float*)d_out;

    cudaFuncSetAttribute(ssim_tile_kernel,
                         cudaFuncAttributeMaxDynamicSharedMemorySize, SMEM_BYTES);

    dim3 grid(IMG_W / TW, IMG_H / TH, NBATCH);   // 32 x 32 x 16
    ssim_tile_kernel<<<grid, 256, SMEM_BYTES>>>(logits, target, out);
}

// round 10
// speedup vs baseline: 1.4611x; 1.0395x over previous
#include <cuda_runtime.h>

// SSIM-with-logits fused kernel for GB300 (sm_103a), single-kernel version.
// input:  d_in[0] = logits  (16,1,1024,1024) f32
//         d_in[1] = target  (16,1,1024,1024) f32
// output: d_out[0] = scalar mean loss (f32)

#define IMG_H 1024
#define IMG_W 1024
#define NBATCH 16
#define TW 32              // tile width  (output)
#define TH 32              // tile height (output)
#define EW 42              // extended width  (TW + 10)
#define EH 42              // extended height (TH + 10)
#define SW 49              // smem stride for s rows (48 cols used; odd -> conflict-free)
#define HT 42              // h transposed: stride per column (conflict-free pairs)
#define MS (TW * HT)       // per-map size of transposed h (1344 floats)
#define NBLK (NBATCH * (IMG_H/TH) * (IMG_W/TW))   // 16384

#define S_FLOATS (2*EH*SW)                 // 4116
#define H_FLOATS (5*MS)                    // 6720
#define SMEM_FLOATS (S_FLOATS + H_FLOATS)  // 10836
#define SMEM_BYTES  (SMEM_FLOATS * 4)      // 43344

__device__ float    g_partial[NBLK];
__device__ unsigned g_count = 0;

typedef unsigned long long u64;

// ---- f32x2 packed helpers (sm_103a) ---------------------------------------
__device__ __forceinline__ u64 pack2(float lo, float hi) {
    u64 r;
    asm("mov.b64 %0, {%1, %2};" : "=l"(r) : "r"(__float_as_uint(lo)), "r"(__float_as_uint(hi)));
    return r;
}
__device__ __forceinline__ void unpack2(u64 v, float& lo, float& hi) {
    unsigned a, b;
    asm("mov.b64 {%0, %1}, %2;" : "=r"(a), "=r"(b) : "l"(v));
    lo = __uint_as_float(a); hi = __uint_as_float(b);
}
__device__ __forceinline__ u64 fma2(u64 a, u64 b, u64 c) {
    u64 d; asm("fma.rn.f32x2 %0, %1, %2, %3;" : "=l"(d) : "l"(a), "l"(b), "l"(c)); return d;
}
__device__ __forceinline__ u64 mul2(u64 a, u64 b) {
    u64 d; asm("mul.rn.f32x2 %0, %1, %2;" : "=l"(d) : "l"(a), "l"(b)); return d;
}
__device__ __forceinline__ u64 add2(u64 a, u64 b) {
    u64 d; asm("add.rn.f32x2 %0, %1, %2;" : "=l"(d) : "l"(a), "l"(b)); return d;
}
__device__ __forceinline__ u64 wpair(float w) {
    unsigned u = __float_as_uint(w);
    return (((u64)u) << 32) | (u64)u;
}

// Gaussian(sigma=1.5, ws=11) taps
#define G0 0.00102838f
#define G1 0.00759875f
#define G2 0.03600077f
#define G3 0.10936084f
#define G4 0.21300546f
#define G5 0.26601163f

// Scalar horizontal conv (FFMA-imm, rt_SMSP=1)
__device__ __forceinline__ float conv11(const float* x) {
    float a =  G0 * x[0];
    a = fmaf(G1, x[1],  a);
    a = fmaf(G2, x[2],  a);
    a = fmaf(G3, x[3],  a);
    a = fmaf(G4, x[4],  a);
    a = fmaf(G5, x[5],  a);
    a = fmaf(G4, x[6],  a);
    a = fmaf(G3, x[7],  a);
    a = fmaf(G2, x[8],  a);
    a = fmaf(G1, x[9],  a);
    a = fmaf(G0, x[10], a);
    return a;
}

// Product conv: conv over elementwise a[i]*b[i] without materializing the array.
__device__ __forceinline__ float conv11p(const float* x, const float* y) {
    float a =  G0 * (x[0] * y[0]);
    a = fmaf(G1, x[1]  * y[1],  a);
    a = fmaf(G2, x[2]  * y[2],  a);
    a = fmaf(G3, x[3]  * y[3],  a);
    a = fmaf(G4, x[4]  * y[4],  a);
    a = fmaf(G5, x[5]  * y[5],  a);
    a = fmaf(G4, x[6]  * y[6],  a);
    a = fmaf(G3, x[7]  * y[7],  a);
    a = fmaf(G2, x[8]  * y[8],  a);
    a = fmaf(G1, x[9]  * y[9],  a);
    a = fmaf(G0, x[10] * y[10], a);
    return a;
}

// Packed vertical conv for one map: produces out-row pairs (r0,r0+1) and (r0+2,r0+3).
__device__ __forceinline__ void vconv(const float* hc, u64& vA, u64& vB) {
    const u64* hp = (const u64*)hc;
    u64 A0 = hp[0], A1 = hp[1], A2 = hp[2], A3 = hp[3], A4 = hp[4], A5 = hp[5], A6 = hp[6];
    float l0,h0,l1,h1,l2,h2,l3,h3,l4,h4,l5,h5,l6,h6;
    unpack2(A0,l0,h0); unpack2(A1,l1,h1); unpack2(A2,l2,h2); unpack2(A3,l3,h3);
    unpack2(A4,l4,h4); unpack2(A5,l5,h5); unpack2(A6,l6,h6);
    u64 p1  = pack2(h0, l1);
    u64 p3  = pack2(h1, l2);
    u64 p5  = pack2(h2, l3);
    u64 p7  = pack2(h3, l4);
    u64 p9  = pack2(h4, l5);
    u64 p11 = pack2(h5, l6);
    u64 a;
    a = mul2(A0, wpair(G0));
    a = fma2(p1, wpair(G1), a);  a = fma2(A1, wpair(G2), a);
    a = fma2(p3, wpair(G3), a);  a = fma2(A2, wpair(G4), a);
    a = fma2(p5, wpair(G5), a);  a = fma2(A3, wpair(G4), a);
    a = fma2(p7, wpair(G3), a);  a = fma2(A4, wpair(G2), a);
    a = fma2(p9, wpair(G1), a);  a = fma2(A5, wpair(G0), a);
    vA = a;
    u64 b;
    b = mul2(A1, wpair(G0));
    b = fma2(p3, wpair(G1), b);  b = fma2(A2, wpair(G2), b);
    b = fma2(p5, wpair(G3), b);  b = fma2(A3, wpair(G4), b);
    b = fma2(p7, wpair(G5), b);  b = fma2(A4, wpair(G4), b);
    b = fma2(p9, wpair(G3), b);  b = fma2(A5, wpair(G2), b);
    b = fma2(p11, wpair(G1), b); b = fma2(A6, wpair(G0), b);
    vB = b;
}

__device__ __forceinline__ float fast_sigmoid(float x) {
    return __fdividef(1.0f, 1.0f + __expf(-x));
}

extern __shared__ float dyn_smem[];

__global__ __launch_bounds__(256, 5)
void ssim_tile_kernel(const float* __restrict__ logits,
                      const float* __restrict__ target,
                      float* __restrict__ out) {
    float* sa = dyn_smem;                // sa[EH][SW]   sigmoid(logits)
    float* sb = dyn_smem + EH * SW;      // sb[EH][SW]   target
    float* h  = dyn_smem + S_FLOATS;     // h[5][TW cols][HT rows]  (transposed)

    const int tid   = threadIdx.x;
    const int tileC = blockIdx.x * TW;
    const int tileR = blockIdx.y * TH;
    const int bz    = blockIdx.z;

    const float* inb = logits + (size_t)bz * (IMG_H * IMG_W);
    const float* tgb = target + (size_t)bz * (IMG_H * IMG_W);

    const bool interior = (blockIdx.x > 0) & (blockIdx.x < (IMG_W/TW - 1)) &
                          (blockIdx.y > 0) & (blockIdx.y < (IMG_H/TH - 1));

    if (interior) {
        // ---- Phase 1 (fast): aligned float4 loads, no reflection --------
        #pragma unroll
        for (int it = 0; it < 2; ++it) {
            int i = tid + it * 256;
            if (i < EH * 12) {
                int er = i / 12;
                int q  = i - er * 12;
                const float4* pr = (const float4*)(inb + (tileR + er - 5) * IMG_W + (tileC - 8));
                const float4* pt = (const float4*)(tgb + (tileR + er - 5) * IMG_W + (tileC - 8));
                float4 xv = pr[q];
                float4 tv = pt[q];
                float* par = sa + er * SW + 4 * q;
                float* pbr = sb + er * SW + 4 * q;
                par[0] = fast_sigmoid(xv.x);
                par[1] = fast_sigmoid(xv.y);
                par[2] = fast_sigmoid(xv.z);
                par[3] = fast_sigmoid(xv.w);
                pbr[0] = tv.x; pbr[1] = tv.y; pbr[2] = tv.z; pbr[3] = tv.w;
            }
        }
    } else {
        // ---- Phase 1 (generic): per-element reflect padding -------------
        for (int i = tid; i < EH * EW; i += 256) {
            int er = i / EW;
            int ec = i - er * EW;
            int gr = tileR + er - 5;
            int gc = tileC + ec - 5;
            if (gr < 0) gr = -gr;
            if (gr > IMG_H - 1) gr = 2 * (IMG_H - 1) - gr;
            if (gc < 0) gc = -gc;
            if (gc > IMG_W - 1) gc = 2 * (IMG_W - 1) - gc;
            float xi = inb[gr * IMG_W + gc];
            float bt = tgb[gr * IMG_W + gc];
            sa[er * SW + ec + 3] = fast_sigmoid(xi);
            sb[er * SW + ec + 3] = bt;
        }
    }
    __syncthreads();

    // ---- Phase 2: combined-map horizontal pass -> transposed h -----------
    // Task = (col-chunk of 8, row): 4*42 = 168 tasks. Each thread loads its
    // a/b windows ONCE and computes all 5 horizontal maps from registers.
    // Task order (chunk = tid/42, r = tid%42) keeps reads (stride 49, x17
    // mod 32) and transposed stores (consecutive r) bank-conflict-free.
    if (tid < 4 * EH) {
        const int chunk = tid / EH;          // 0..3
        const int r     = tid - chunk * EH;  // 0..41
        const float* arow = sa + r * SW + chunk * 8 + 3;
        const float* brow = sb + r * SW + chunk * 8 + 3;
        float* hdst = h + (chunk * 8) * HT + r;   // + m*MS + c*HT per output

        float wa[18], wb[18];
        #pragma unroll
        for (int i = 0; i < 18; ++i) wa[i] = arow[i];
        #pragma unroll
        for (int c = 0; c < 8; ++c) hdst[0 * MS + c * HT] = conv11(&wa[c]);

        #pragma unroll
        for (int i = 0; i < 18; ++i) wb[i] = brow[i];
        #pragma unroll
        for (int c = 0; c < 8; ++c) hdst[1 * MS + c * HT] = conv11(&wb[c]);

        #pragma unroll
        for (int c = 0; c < 8; ++c) hdst[4 * MS + c * HT] = conv11p(&wa[c], &wb[c]);

        #pragma unroll
        for (int i = 0; i < 18; ++i) wa[i] *= wa[i];
        #pragma unroll
        for (int c = 0; c < 8; ++c) hdst[2 * MS + c * HT] = conv11(&wa[c]);

        #pragma unroll
        for (int i = 0; i < 18; ++i) wb[i] *= wb[i];
        #pragma unroll
        for (int c = 0; c < 8; ++c) hdst[3 * MS + c * HT] = conv11(&wb[c]);
    }
    __syncthreads();

    // ---- Phase 3: packed vertical pass + SSIM ----------------------------
    const int c  = tid & 31;
    const int r0 = (tid >> 5) * 4;
    const float* hb = h + c * HT + r0;

    const u64 C1p = wpair(1.0e-4f);
    const u64 C2p = wpair(9.0e-4f);
    const u64 TWOp = wpair(2.0f);
    const u64 N1p = wpair(-1.0f);

    u64 muA1, muB1, muA2, muB2;
    vconv(hb + 0 * MS, muA1, muB1);
    vconv(hb + 1 * MS, muA2, muB2);

    u64 m12A  = mul2(muA1, muA2);
    u64 m12B  = mul2(muB1, muB2);
    u64 den1A = fma2(muA2, muA2, fma2(muA1, muA1, C1p));   // m11+m22+C1
    u64 den1B = fma2(muB2, muB2, fma2(muB1, muB1, C1p));
    u64 msumA = fma2(C1p, N1p, den1A);                      // m11+m22
    u64 msumB = fma2(C1p, N1p, den1B);

    u64 eA2, eB2, tA, tB;
    vconv(hb + 2 * MS, eA2, eB2);   // E[a^2]
    vconv(hb + 3 * MS, tA, tB);     // E[b^2]
    u64 sEA = add2(eA2, tA);
    u64 sEB = add2(eB2, tB);

    u64 eabA, eabB;
    vconv(hb + 4 * MS, eabA, eabB); // E[ab]

    u64 den2A = add2(fma2(msumA, N1p, sEA), C2p);  // s11+s22+C2
    u64 den2B = add2(fma2(msumB, N1p, sEB), C2p);
    u64 s12A  = fma2(m12A, N1p, eabA);             // sigma12
    u64 s12B  = fma2(m12B, N1p, eabB);
    u64 numA  = mul2(fma2(TWOp, m12A, C1p), fma2(TWOp, s12A, C2p));
    u64 numB  = mul2(fma2(TWOp, m12B, C1p), fma2(TWOp, s12B, C2p));
    u64 denA  = mul2(den1A, den2A);
    u64 denB  = mul2(den1B, den2B);

    float n0, n1, n2, n3, d0, d1, d2, d3;
    unpack2(numA, n0, n1); unpack2(numB, n2, n3);
    unpack2(denA, d0, d1); unpack2(denB, d2, d3);

    float lsum = 0.0f;
    {
        float l;
        l = 0.5f - 0.5f * __fdividef(n0, d0); lsum += fminf(fmaxf(l, 0.0f), 0.5f);
        l = 0.5f - 0.5f * __fdividef(n1, d1); lsum += fminf(fmaxf(l, 0.0f), 0.5f);
        l = 0.5f - 0.5f * __fdividef(n2, d2); lsum += fminf(fmaxf(l, 0.0f), 0.5f);
        l = 0.5f - 0.5f * __fdividef(n3, d3); lsum += fminf(fmaxf(l, 0.0f), 0.5f);
    }

    // ---- Phase 4: block reduction -> g_partial -------------------------
    #pragma unroll
    for (int o = 16; o; o >>= 1)
        lsum += __shfl_xor_sync(0xffffffffu, lsum, o);
    __shared__ float wsum[8];
    __shared__ bool  is_last;
    if ((tid & 31) == 0) wsum[tid >> 5] = lsum;
    __syncthreads();
    if (tid == 0) {
        float t = 0.0f;
        #pragma unroll
        for (int i = 0; i < 8; ++i) t += wsum[i];
        int bid = (blockIdx.z * gridDim.y + blockIdx.y) * gridDim.x + blockIdx.x;
        g_partial[bid] = t;
        __threadfence();
        unsigned old = atomicInc(&g_count, NBLK - 1);
        is_last = (old == NBLK - 1);
    }
    __syncthreads();

    // ---- Phase 5: last block performs the deterministic final sum -------
    if (is_last) {
        __threadfence();
        const float4* p = (const float4*)g_partial;
        double acc = 0.0;
        #pragma unroll
        for (int i = 0; i < NBLK / 4 / 256; ++i) {     // 16 iterations
            float4 q = __ldcg(&p[tid + i * 256]);
            acc += (double)q.x + (double)q.y + (double)q.z + (double)q.w;
        }
        #pragma unroll
        for (int o = 16; o; o >>= 1)
            acc += __shfl_xor_sync(0xffffffffu, acc, o);
        __shared__ double dsum[8];
        if ((tid & 31) == 0) dsum[tid >> 5] = acc;
        __syncthreads();
        if (tid == 0) {
            double t = 0.0;
            #pragma unroll
            for (int i = 0; i < 8; ++i) t += dsum[i];
            out[0] = (float)(t * (1.0 / ((double)NBATCH * IMG_H * IMG_W)));
        }
    }
}

extern "C" void kernel_launch(void* const* d_in, const int* in_sizes, int n_in,
                              void* d_out, int out_size) {
    const float* logits = (const float*)d_in[0];
    const float* target = (const float*)d_in[1];
    float* out = (float*)d_out;

    cudaFuncSetAttribute(ssim_tile_kernel,
                         cudaFuncAttributeMaxDynamicSharedMemorySize, SMEM_BYTES);

    dim3 grid(IMG_W / TW, IMG_H / TH, NBATCH);   // 32 x 32 x 16
    ssim_tile_kernel<<<grid, 256, SMEM_BYTES>>>(logits, target, out);
}